// round 1
// baseline (speedup 1.0000x reference)
#include <cuda_runtime.h>
#include <cuda_bf16.h>

#define BN 2
#define BT 2048
#define BE 1024
#define BH 16
#define DH 64

// Scratch (allocation-free rule: __device__ globals)
__device__ float g_Q[(size_t)BN * BH * BT * DH]; // [n,h,t,d]
__device__ float g_K[(size_t)BN * BH * BT * DH];
__device__ float g_V[(size_t)BN * BH * BT * DH];
__device__ float g_C[(size_t)BN * BT * BH * DH]; // concat layout [n,t,h,d]

// ---------------------------------------------------------------------------
// Projection: Out[n,h,t,d] = sum_e X[n,t,e] * W[h,e,d]
// grid: (T/64, N*H, 3={q,k,v}), 256 threads, 64x64 tile, 4x4 microtile
// ---------------------------------------------------------------------------
__global__ __launch_bounds__(256) void proj_kernel(
    const float* __restrict__ qin, const float* __restrict__ kin,
    const float* __restrict__ vin,
    const float* __restrict__ Wq, const float* __restrict__ Wk,
    const float* __restrict__ Wv)
{
    int z  = blockIdx.z;
    int nh = blockIdx.y;
    int n = nh >> 4, h = nh & 15;
    int t0 = blockIdx.x * 64;

    const float* X = (z == 0 ? qin : z == 1 ? kin : vin)
                     + (size_t)n * BT * BE + (size_t)t0 * BE;
    const float* W = (z == 0 ? Wq : z == 1 ? Wk : Wv) + (size_t)h * BE * DH;
    float* O = (z == 0 ? g_Q : z == 1 ? g_K : g_V) + ((size_t)nh * BT + t0) * DH;

    __shared__ float Xs[64][17];  // [t][e-chunk], padded
    __shared__ float Ws[16][64];  // [e-chunk][d]

    int tid = threadIdx.x;
    int ty = tid >> 4, tx = tid & 15;

    float acc[4][4];
#pragma unroll
    for (int i = 0; i < 4; i++)
#pragma unroll
        for (int j = 0; j < 4; j++) acc[i][j] = 0.f;

    for (int e0 = 0; e0 < BE; e0 += 16) {
#pragma unroll
        for (int t = 0; t < 4; ++t) {
            int li = tid + t * 256;          // 1024 elems
            int r = li >> 4, c = li & 15;
            Xs[r][c] = X[(size_t)r * BE + e0 + c];
        }
#pragma unroll
        for (int t = 0; t < 4; ++t) {
            int li = tid + t * 256;          // 1024 elems
            int r = li >> 6, c = li & 63;
            Ws[r][c] = W[(size_t)(e0 + r) * DH + c];
        }
        __syncthreads();
#pragma unroll
        for (int kk = 0; kk < 16; ++kk) {
            float a[4], b[4];
#pragma unroll
            for (int i = 0; i < 4; i++) a[i] = Xs[ty * 4 + i][kk];
#pragma unroll
            for (int j = 0; j < 4; j++) b[j] = Ws[kk][tx * 4 + j];
#pragma unroll
            for (int i = 0; i < 4; i++)
#pragma unroll
                for (int j = 0; j < 4; j++) acc[i][j] += a[i] * b[j];
        }
        __syncthreads();
    }
#pragma unroll
    for (int i = 0; i < 4; i++)
#pragma unroll
        for (int j = 0; j < 4; j++)
            O[(size_t)(ty * 4 + i) * DH + tx * 4 + j] = acc[i][j];
}

// ---------------------------------------------------------------------------
// Flash attention (causal): per (qtile, n*h) block of 64 queries.
// 256 threads = 64 rows x 4 d-segments. Q in regs (16f/thread), online softmax.
// Writes concat layout g_C[n, t, h, d].
// ---------------------------------------------------------------------------
__global__ __launch_bounds__(256) void flash_kernel()
{
    int qt = blockIdx.x;
    int nh = blockIdx.y;
    int n = nh >> 4, h = nh & 15;
    int tid = threadIdx.x;
    int row = tid >> 2, seg = tid & 3;

    const float* Qb = g_Q + ((size_t)nh * BT + (size_t)qt * 64) * DH;
    const float* Kb = g_K + (size_t)nh * BT * DH;
    const float* Vb = g_V + (size_t)nh * BT * DH;

    __shared__ float Ks[64][64];
    __shared__ float Vs[64][64];

    float q[16];
    {
        const float4* qs =
            reinterpret_cast<const float4*>(Qb + (size_t)row * DH + seg * 16);
#pragma unroll
        for (int i = 0; i < 4; i++) {
            float4 t = qs[i];
            q[i * 4 + 0] = t.x; q[i * 4 + 1] = t.y;
            q[i * 4 + 2] = t.z; q[i * 4 + 3] = t.w;
        }
    }

    float o[16];
#pragma unroll
    for (int i = 0; i < 16; i++) o[i] = 0.f;
    float m = -1e30f, l = 0.f;

    for (int kt = 0; kt <= qt; ++kt) {
        const float4* ksrc =
            reinterpret_cast<const float4*>(Kb + (size_t)kt * 64 * DH);
        const float4* vsrc =
            reinterpret_cast<const float4*>(Vb + (size_t)kt * 64 * DH);
        float4* kdst = reinterpret_cast<float4*>(&Ks[0][0]);
        float4* vdst = reinterpret_cast<float4*>(&Vs[0][0]);
#pragma unroll
        for (int it = 0; it < 4; ++it) {
            kdst[tid + it * 256] = ksrc[tid + it * 256];
            vdst[tid + it * 256] = vsrc[tid + it * 256];
        }
        __syncthreads();

        // partial scores over this thread's 16-d segment, all 64 keys
        float s[64];
#pragma unroll
        for (int k = 0; k < 64; ++k) {
            const float* kr = &Ks[k][seg * 16];
            float a = 0.f;
#pragma unroll
            for (int i = 0; i < 16; ++i) a += q[i] * kr[i];
            s[k] = a;
        }
        // sum across the 4 segments of this row (lanes row*4 .. row*4+3)
#pragma unroll
        for (int k = 0; k < 64; ++k) {
            s[k] += __shfl_xor_sync(0xffffffffu, s[k], 1);
            s[k] += __shfl_xor_sync(0xffffffffu, s[k], 2);
        }
#pragma unroll
        for (int k = 0; k < 64; ++k) s[k] *= 0.125f;  // 1/sqrt(DH)

        if (kt == qt) {  // causal mask inside diagonal tile
#pragma unroll
            for (int k = 0; k < 64; ++k)
                if (k > row) s[k] = -1e30f;
        }

        float mt = m;
#pragma unroll
        for (int k = 0; k < 64; ++k) mt = fmaxf(mt, s[k]);
        float corr = __expf(m - mt);
        float lsum = 0.f;
#pragma unroll
        for (int k = 0; k < 64; ++k) {
            float p = __expf(s[k] - mt);
            s[k] = p;
            lsum += p;
        }
        l = l * corr + lsum;
        m = mt;
#pragma unroll
        for (int i = 0; i < 16; ++i) o[i] *= corr;
#pragma unroll
        for (int k = 0; k < 64; ++k) {
            float p = s[k];
            const float* vr = &Vs[k][seg * 16];
#pragma unroll
            for (int i = 0; i < 16; ++i) o[i] += p * vr[i];
        }
        __syncthreads();
    }

    float inv = 1.0f / l;
    float* dst = g_C + (((size_t)n * BT + (size_t)qt * 64 + row) * BH + h) * DH
                 + seg * 16;
#pragma unroll
    for (int i = 0; i < 16; ++i) dst[i] = o[i] * inv;
}

// ---------------------------------------------------------------------------
// Output projection: out[r, e] = sum_k C[r, k] * Wo[e, k] + bo[e]
// r over N*T. grid (N*T/64, E/64), 256 threads, 4x4 microtile.
// ---------------------------------------------------------------------------
__global__ __launch_bounds__(256) void outproj_kernel(
    const float* __restrict__ Wo, const float* __restrict__ bo,
    float* __restrict__ out)
{
    int r0 = blockIdx.x * 64;
    int c0 = blockIdx.y * 64;

    __shared__ float As[64][17];
    __shared__ float Bs[64][17];

    int tid = threadIdx.x;
    int ty = tid >> 4, tx = tid & 15;

    float acc[4][4];
#pragma unroll
    for (int i = 0; i < 4; i++)
#pragma unroll
        for (int j = 0; j < 4; j++) acc[i][j] = 0.f;

    for (int k0 = 0; k0 < BE; k0 += 16) {
#pragma unroll
        for (int t = 0; t < 4; ++t) {
            int li = tid + t * 256;
            int r = li >> 4, c = li & 15;
            As[r][c] = g_C[(size_t)(r0 + r) * BE + k0 + c];
            Bs[r][c] = Wo[(size_t)(c0 + r) * BE + k0 + c];
        }
        __syncthreads();
#pragma unroll
        for (int kk = 0; kk < 16; ++kk) {
            float a[4], b[4];
#pragma unroll
            for (int i = 0; i < 4; i++) a[i] = As[ty * 4 + i][kk];
#pragma unroll
            for (int j = 0; j < 4; j++) b[j] = Bs[tx * 4 + j][kk];
#pragma unroll
            for (int i = 0; i < 4; i++)
#pragma unroll
                for (int j = 0; j < 4; j++) acc[i][j] += a[i] * b[j];
        }
        __syncthreads();
    }
#pragma unroll
    for (int i = 0; i < 4; i++) {
#pragma unroll
        for (int j = 0; j < 4; j++) {
            int c = c0 + tx * 4 + j;
            out[(size_t)(r0 + ty * 4 + i) * BE + c] = acc[i][j] + bo[c];
        }
    }
}

// ---------------------------------------------------------------------------
extern "C" void kernel_launch(void* const* d_in, const int* in_sizes, int n_in,
                              void* d_out, int out_size)
{
    const float* q  = (const float*)d_in[0];
    const float* k  = (const float*)d_in[1];
    const float* v  = (const float*)d_in[2];
    // d_in[3] = mask (int32 tril) — causality implemented structurally
    const float* Wq = (const float*)d_in[4];
    const float* Wk = (const float*)d_in[5];
    const float* Wv = (const float*)d_in[6];
    const float* Wo = (const float*)d_in[7];
    const float* bo = (const float*)d_in[8];
    float* out = (float*)d_out;

    proj_kernel<<<dim3(BT / 64, BN * BH, 3), 256>>>(q, k, v, Wq, Wk, Wv);
    flash_kernel<<<dim3(BT / 64, BN * BH), 256>>>();
    outproj_kernel<<<dim3(BN * BT / 64, BE / 64), 256>>>(Wo, bo, out);
}

// round 2
// speedup vs baseline: 1.0325x; 1.0325x over previous
#include <cuda_runtime.h>
#include <cuda_bf16.h>

#define BN 2
#define BT 2048
#define BE 1024
#define BH 16
#define DH 64

// Scratch (allocation-free rule: __device__ globals)
__device__ float g_Q[(size_t)BN * BH * BT * DH]; // [n,h,t,d]
__device__ float g_K[(size_t)BN * BH * BT * DH];
__device__ float g_V[(size_t)BN * BH * BT * DH];
__device__ float g_C[(size_t)BN * BT * BH * DH]; // concat layout [n,t,h,d]

// ---------------------------------------------------------------------------
// Projection: Out[n,h,t,d] = sum_e X[n,t,e] * W[h,e,d]
// grid: (T/64, N*H, 3={q,k,v}), 256 threads, 64x64 tile, 4x4 microtile.
// Shared tiles stored k-major with pitch 68 so inner loop is 2xLDS128 + 16 FFMA.
// ---------------------------------------------------------------------------
__global__ __launch_bounds__(256) void proj_kernel(
    const float* __restrict__ qin, const float* __restrict__ kin,
    const float* __restrict__ vin,
    const float* __restrict__ Wq, const float* __restrict__ Wk,
    const float* __restrict__ Wv)
{
    int z  = blockIdx.z;
    int nh = blockIdx.y;
    int t0 = blockIdx.x * 64;
    int n = nh >> 4;

    const float* X = (z == 0 ? qin : z == 1 ? kin : vin)
                     + (size_t)n * BT * BE + (size_t)t0 * BE;
    const float* W = (z == 0 ? Wq : z == 1 ? Wk : Wv)
                     + (size_t)(nh & 15) * BE * DH;
    float* O = (z == 0 ? g_Q : z == 1 ? g_K : g_V) + ((size_t)nh * BT + t0) * DH;

    __shared__ float Xs[16][68];  // [e-chunk][t]  (k-major)
    __shared__ float Ws[16][68];  // [e-chunk][d]  (k-major)

    int tid = threadIdx.x;
    int ty = tid >> 4, tx = tid & 15;

    float acc[4][4];
#pragma unroll
    for (int i = 0; i < 4; i++)
#pragma unroll
        for (int j = 0; j < 4; j++) acc[i][j] = 0.f;

    for (int e0 = 0; e0 < BE; e0 += 16) {
#pragma unroll
        for (int t = 0; t < 4; ++t) {
            int li = tid + t * 256;          // 1024 elems
            int r = li >> 4, c = li & 15;    // r: t-row, c: e
            Xs[c][r] = X[(size_t)r * BE + e0 + c];
        }
#pragma unroll
        for (int t = 0; t < 4; ++t) {
            int li = tid + t * 256;          // 1024 elems
            int r = li >> 6, c = li & 63;    // r: e, c: d
            Ws[r][c] = W[(size_t)(e0 + r) * DH + c];
        }
        __syncthreads();
#pragma unroll
        for (int kk = 0; kk < 16; ++kk) {
            float4 a = *reinterpret_cast<const float4*>(&Xs[kk][ty * 4]);
            float4 b = *reinterpret_cast<const float4*>(&Ws[kk][tx * 4]);
            acc[0][0] += a.x * b.x; acc[0][1] += a.x * b.y;
            acc[0][2] += a.x * b.z; acc[0][3] += a.x * b.w;
            acc[1][0] += a.y * b.x; acc[1][1] += a.y * b.y;
            acc[1][2] += a.y * b.z; acc[1][3] += a.y * b.w;
            acc[2][0] += a.z * b.x; acc[2][1] += a.z * b.y;
            acc[2][2] += a.z * b.z; acc[2][3] += a.z * b.w;
            acc[3][0] += a.w * b.x; acc[3][1] += a.w * b.y;
            acc[3][2] += a.w * b.z; acc[3][3] += a.w * b.w;
        }
        __syncthreads();
    }
#pragma unroll
    for (int i = 0; i < 4; i++) {
        float4 v = make_float4(acc[i][0], acc[i][1], acc[i][2], acc[i][3]);
        *reinterpret_cast<float4*>(&O[(size_t)(ty * 4 + i) * DH + tx * 4]) = v;
    }
}

// ---------------------------------------------------------------------------
// Flash attention (causal): per (qtile, n*h) block of 64 queries.
// 256 threads = 64 rows x 4 d-segments. Q in regs (16f/thread, pre-scaled),
// online softmax, float4 shared reads. Writes concat layout g_C[n, t, h, d].
// ---------------------------------------------------------------------------
__global__ __launch_bounds__(256) void flash_kernel()
{
    int qt = blockIdx.x;
    int nh = blockIdx.y;
    int n = nh >> 4, h = nh & 15;
    int tid = threadIdx.x;
    int row = tid >> 2, seg = tid & 3;

    const float* Qb = g_Q + ((size_t)nh * BT + (size_t)qt * 64) * DH;
    const float* Kb = g_K + (size_t)nh * BT * DH;
    const float* Vb = g_V + (size_t)nh * BT * DH;

    __shared__ float Ks[64][64];
    __shared__ float Vs[64][64];

    float q[16];
    {
        const float4* qs =
            reinterpret_cast<const float4*>(Qb + (size_t)row * DH + seg * 16);
#pragma unroll
        for (int i = 0; i < 4; i++) {
            float4 t = qs[i];
            q[i * 4 + 0] = t.x * 0.125f; q[i * 4 + 1] = t.y * 0.125f;
            q[i * 4 + 2] = t.z * 0.125f; q[i * 4 + 3] = t.w * 0.125f;
        }
    }

    float o[16];
#pragma unroll
    for (int i = 0; i < 16; i++) o[i] = 0.f;
    float m = -1e30f, l = 0.f;

    for (int kt = 0; kt <= qt; ++kt) {
        const float4* ksrc =
            reinterpret_cast<const float4*>(Kb + (size_t)kt * 64 * DH);
        const float4* vsrc =
            reinterpret_cast<const float4*>(Vb + (size_t)kt * 64 * DH);
        float4* kdst = reinterpret_cast<float4*>(&Ks[0][0]);
        float4* vdst = reinterpret_cast<float4*>(&Vs[0][0]);
#pragma unroll
        for (int it = 0; it < 4; ++it) {
            kdst[tid + it * 256] = ksrc[tid + it * 256];
            vdst[tid + it * 256] = vsrc[tid + it * 256];
        }
        __syncthreads();

        // partial scores over this thread's 16-d segment, all 64 keys
        float s[64];
#pragma unroll
        for (int k = 0; k < 64; ++k) {
            const float4* kr =
                reinterpret_cast<const float4*>(&Ks[k][seg * 16]);
            float4 k0 = kr[0], k1 = kr[1], k2 = kr[2], k3 = kr[3];
            float a = q[0] * k0.x;
            a += q[1] * k0.y;  a += q[2] * k0.z;  a += q[3] * k0.w;
            a += q[4] * k1.x;  a += q[5] * k1.y;  a += q[6] * k1.z;
            a += q[7] * k1.w;  a += q[8] * k2.x;  a += q[9] * k2.y;
            a += q[10] * k2.z; a += q[11] * k2.w; a += q[12] * k3.x;
            a += q[13] * k3.y; a += q[14] * k3.z; a += q[15] * k3.w;
            s[k] = a;
        }
        // sum across the 4 segments of this row (lanes row*4 .. row*4+3)
#pragma unroll
        for (int k = 0; k < 64; ++k) {
            s[k] += __shfl_xor_sync(0xffffffffu, s[k], 1);
            s[k] += __shfl_xor_sync(0xffffffffu, s[k], 2);
        }

        if (kt == qt) {  // causal mask inside diagonal tile
#pragma unroll
            for (int k = 0; k < 64; ++k)
                if (k > row) s[k] = -1e30f;
        }

        float mt = m;
#pragma unroll
        for (int k = 0; k < 64; ++k) mt = fmaxf(mt, s[k]);
        float corr = __expf(m - mt);
        float lsum = 0.f;
#pragma unroll
        for (int k = 0; k < 64; ++k) {
            float p = __expf(s[k] - mt);
            s[k] = p;
            lsum += p;
        }
        l = l * corr + lsum;
        m = mt;
#pragma unroll
        for (int i = 0; i < 16; ++i) o[i] *= corr;
#pragma unroll
        for (int k = 0; k < 64; ++k) {
            float p = s[k];
            const float4* vr =
                reinterpret_cast<const float4*>(&Vs[k][seg * 16]);
            float4 v0 = vr[0], v1 = vr[1], v2 = vr[2], v3 = vr[3];
            o[0]  += p * v0.x; o[1]  += p * v0.y;
            o[2]  += p * v0.z; o[3]  += p * v0.w;
            o[4]  += p * v1.x; o[5]  += p * v1.y;
            o[6]  += p * v1.z; o[7]  += p * v1.w;
            o[8]  += p * v2.x; o[9]  += p * v2.y;
            o[10] += p * v2.z; o[11] += p * v2.w;
            o[12] += p * v3.x; o[13] += p * v3.y;
            o[14] += p * v3.z; o[15] += p * v3.w;
        }
        __syncthreads();
    }

    float inv = 1.0f / l;
    float* dst = g_C + (((size_t)n * BT + (size_t)qt * 64 + row) * BH + h) * DH
                 + seg * 16;
#pragma unroll
    for (int i = 0; i < 4; ++i) {
        float4 v = make_float4(o[i * 4 + 0] * inv, o[i * 4 + 1] * inv,
                               o[i * 4 + 2] * inv, o[i * 4 + 3] * inv);
        *reinterpret_cast<float4*>(dst + i * 4) = v;
    }
}

// ---------------------------------------------------------------------------
// Output projection: out[r, e] = sum_k C[r, k] * Wo[e, k] + bo[e]
// r over N*T. grid (N*T/64, E/64), 256 threads, 4x4 microtile, k-major smem.
// ---------------------------------------------------------------------------
__global__ __launch_bounds__(256) void outproj_kernel(
    const float* __restrict__ Wo, const float* __restrict__ bo,
    float* __restrict__ out)
{
    int r0 = blockIdx.x * 64;
    int c0 = blockIdx.y * 64;

    __shared__ float As[16][68];  // [k][r]
    __shared__ float Bs[16][68];  // [k][e]

    int tid = threadIdx.x;
    int ty = tid >> 4, tx = tid & 15;

    float acc[4][4];
#pragma unroll
    for (int i = 0; i < 4; i++)
#pragma unroll
        for (int j = 0; j < 4; j++) acc[i][j] = 0.f;

    for (int k0 = 0; k0 < BE; k0 += 16) {
#pragma unroll
        for (int t = 0; t < 4; ++t) {
            int li = tid + t * 256;
            int r = li >> 4, c = li & 15;
            As[c][r] = g_C[(size_t)(r0 + r) * BE + k0 + c];
            Bs[c][r] = Wo[(size_t)(c0 + r) * BE + k0 + c];
        }
        __syncthreads();
#pragma unroll
        for (int kk = 0; kk < 16; ++kk) {
            float4 a = *reinterpret_cast<const float4*>(&As[kk][ty * 4]);
            float4 b = *reinterpret_cast<const float4*>(&Bs[kk][tx * 4]);
            acc[0][0] += a.x * b.x; acc[0][1] += a.x * b.y;
            acc[0][2] += a.x * b.z; acc[0][3] += a.x * b.w;
            acc[1][0] += a.y * b.x; acc[1][1] += a.y * b.y;
            acc[1][2] += a.y * b.z; acc[1][3] += a.y * b.w;
            acc[2][0] += a.z * b.x; acc[2][1] += a.z * b.y;
            acc[2][2] += a.z * b.z; acc[2][3] += a.z * b.w;
            acc[3][0] += a.w * b.x; acc[3][1] += a.w * b.y;
            acc[3][2] += a.w * b.z; acc[3][3] += a.w * b.w;
        }
        __syncthreads();
    }
#pragma unroll
    for (int i = 0; i < 4; i++) {
        int r = r0 + ty * 4 + i;
        int c = c0 + tx * 4;
        float4 v = make_float4(acc[i][0] + bo[c + 0], acc[i][1] + bo[c + 1],
                               acc[i][2] + bo[c + 2], acc[i][3] + bo[c + 3]);
        *reinterpret_cast<float4*>(&out[(size_t)r * BE + c]) = v;
    }
}

// ---------------------------------------------------------------------------
extern "C" void kernel_launch(void* const* d_in, const int* in_sizes, int n_in,
                              void* d_out, int out_size)
{
    const float* q  = (const float*)d_in[0];
    const float* k  = (const float*)d_in[1];
    const float* v  = (const float*)d_in[2];
    // d_in[3] = mask (int32 tril) — causality implemented structurally
    const float* Wq = (const float*)d_in[4];
    const float* Wk = (const float*)d_in[5];
    const float* Wv = (const float*)d_in[6];
    const float* Wo = (const float*)d_in[7];
    const float* bo = (const float*)d_in[8];
    float* out = (float*)d_out;

    proj_kernel<<<dim3(BT / 64, BN * BH, 3), 256>>>(q, k, v, Wq, Wk, Wv);
    flash_kernel<<<dim3(BT / 64, BN * BH), 256>>>();
    outproj_kernel<<<dim3(BN * BT / 64, BE / 64), 256>>>(Wo, bo, out);
}

// round 3
// speedup vs baseline: 1.6780x; 1.6252x over previous
#include <cuda_runtime.h>
#include <cuda_bf16.h>

#define BN 2
#define BT 2048
#define BE 1024
#define BH 16
#define DH 64

// ---- packed f32x2 helpers (sm_103a 2x fp32) --------------------------------
#define FMA2(d, a, b) asm("fma.rn.f32x2 %0, %1, %2, %0;" : "+l"(d) : "l"(a), "l"(b))
#define MUL2(d, a, b) asm("mul.rn.f32x2 %0, %1, %2;" : "=l"(d) : "l"(a), "l"(b))
#define ADD2(d, a, b) asm("add.rn.f32x2 %0, %1, %2;" : "=l"(d) : "l"(a), "l"(b))
#define DUP2(out, x) do { unsigned __du = __float_as_uint(x); \
    asm("mov.b64 %0, {%1, %1};" : "=l"(out) : "r"(__du)); } while (0)
#define UNPK2(lo, hi, p) asm("mov.b64 {%0, %1}, %2;" : "=r"(lo), "=r"(hi) : "l"(p))

// Scratch (allocation-free rule: __device__ globals)
__device__ float g_Q[(size_t)BN * BH * BT * DH]; // [n,h,t,d]
__device__ float g_K[(size_t)BN * BH * BT * DH];
__device__ float g_V[(size_t)BN * BH * BT * DH];
__device__ float g_C[(size_t)BN * BT * BH * DH]; // concat layout [n,t,h,d]

// ---------------------------------------------------------------------------
// Projection: Out[n,h,t,d] = sum_e X[n,t,e] * W[h,e,d]
// 128t x 64d tile, 256 threads, microtile 8t x 4d, f32x2 packed over d-pairs.
// ---------------------------------------------------------------------------
__global__ __launch_bounds__(256) void proj_kernel(
    const float* __restrict__ qin, const float* __restrict__ kin,
    const float* __restrict__ vin,
    const float* __restrict__ Wq, const float* __restrict__ Wk,
    const float* __restrict__ Wv)
{
    int z  = blockIdx.z;
    int nh = blockIdx.y;
    int t0 = blockIdx.x * 128;
    int n = nh >> 4;

    const float* X = (z == 0 ? qin : z == 1 ? kin : vin)
                     + (size_t)n * BT * BE + (size_t)t0 * BE;
    const float* W = (z == 0 ? Wq : z == 1 ? Wk : Wv)
                     + (size_t)(nh & 15) * BE * DH;
    float* O = (z == 0 ? g_Q : z == 1 ? g_K : g_V) + ((size_t)nh * BT + t0) * DH;

    __shared__ __align__(16) float Xs[16][132];  // [e-chunk][t], pitch 132
    __shared__ __align__(16) float Ws[16][64];   // [e-chunk][d]

    int tid = threadIdx.x;
    int ty = tid >> 4, tx = tid & 15;

    unsigned long long acc2[8][2];
#pragma unroll
    for (int i = 0; i < 8; i++) { acc2[i][0] = 0ULL; acc2[i][1] = 0ULL; }

    for (int e0 = 0; e0 < BE; e0 += 16) {
#pragma unroll
        for (int it = 0; it < 8; ++it) {              // 128x16 = 2048 elems
            int li = tid + it * 256;
            int c = li & 15, r = li >> 4;
            Xs[c][r] = X[(size_t)r * BE + e0 + c];
        }
#pragma unroll
        for (int it = 0; it < 4; ++it) {              // 16x64 = 1024 elems
            int li = tid + it * 256;
            int d = li & 63, r = li >> 6;
            Ws[r][d] = W[(size_t)(e0 + r) * DH + d];
        }
        __syncthreads();
#pragma unroll
        for (int kk = 0; kk < 16; ++kk) {
            float4 a0 = *reinterpret_cast<const float4*>(&Xs[kk][ty * 8]);
            float4 a1 = *reinterpret_cast<const float4*>(&Xs[kk][ty * 8 + 4]);
            ulonglong2 b = *reinterpret_cast<const ulonglong2*>(&Ws[kk][tx * 4]);
            unsigned long long da;
            DUP2(da, a0.x); FMA2(acc2[0][0], da, b.x); FMA2(acc2[0][1], da, b.y);
            DUP2(da, a0.y); FMA2(acc2[1][0], da, b.x); FMA2(acc2[1][1], da, b.y);
            DUP2(da, a0.z); FMA2(acc2[2][0], da, b.x); FMA2(acc2[2][1], da, b.y);
            DUP2(da, a0.w); FMA2(acc2[3][0], da, b.x); FMA2(acc2[3][1], da, b.y);
            DUP2(da, a1.x); FMA2(acc2[4][0], da, b.x); FMA2(acc2[4][1], da, b.y);
            DUP2(da, a1.y); FMA2(acc2[5][0], da, b.x); FMA2(acc2[5][1], da, b.y);
            DUP2(da, a1.z); FMA2(acc2[6][0], da, b.x); FMA2(acc2[6][1], da, b.y);
            DUP2(da, a1.w); FMA2(acc2[7][0], da, b.x); FMA2(acc2[7][1], da, b.y);
        }
        __syncthreads();
    }
#pragma unroll
    for (int i = 0; i < 8; i++) {
        ulonglong2 v;
        v.x = acc2[i][0]; v.y = acc2[i][1];
        *reinterpret_cast<ulonglong2*>(
            &O[(size_t)(ty * 8 + i) * DH + tx * 4]) = v;
    }
}

// ---------------------------------------------------------------------------
// Flash attention (causal): 64 q-rows per block, 256 threads = 64 rows x 4 segs.
// Each thread owns 16 interleaved keys (k = 4i+seg) with FULL d=64 dots.
// q and o live as 32 f32x2 register pairs. No per-tile score shuffles.
// ---------------------------------------------------------------------------
__global__ __launch_bounds__(256) void flash_kernel()
{
    int qt = (BT / 64 - 1) - blockIdx.x;   // big tiles first (wave balance)
    int nh = blockIdx.y;
    int n = nh >> 4, h = nh & 15;
    int tid = threadIdx.x;
    int row = tid >> 2, seg = tid & 3;
    int row_g = qt * 64 + row;

    const float* Qb = g_Q + ((size_t)nh * BT + (size_t)qt * 64) * DH;
    const float* Kb = g_K + (size_t)nh * BT * DH;
    const float* Vb = g_V + (size_t)nh * BT * DH;

    __shared__ __align__(16) float Ks[64][68];
    __shared__ __align__(16) float Vs[64][68];

    unsigned long long q2[32], o2[32];
    {
        const ulonglong2* qp =
            reinterpret_cast<const ulonglong2*>(Qb + (size_t)row * DH);
        unsigned long long sc2; DUP2(sc2, 0.125f);   // 1/sqrt(DH)
#pragma unroll
        for (int j = 0; j < 16; ++j) {
            ulonglong2 t = qp[j];
            MUL2(q2[2 * j], t.x, sc2);
            MUL2(q2[2 * j + 1], t.y, sc2);
        }
    }
#pragma unroll
    for (int j = 0; j < 32; ++j) o2[j] = 0ULL;
    float m = -1e30f, l = 0.f;

    for (int kt = 0; kt <= qt; ++kt) {
        const float4* ksrc =
            reinterpret_cast<const float4*>(Kb + (size_t)kt * 64 * DH);
        const float4* vsrc =
            reinterpret_cast<const float4*>(Vb + (size_t)kt * 64 * DH);
#pragma unroll
        for (int it = 0; it < 4; ++it) {
            int li = tid + it * 256;
            int c = li & 15, r = li >> 4;
            float4 kv = ksrc[r * 16 + c];
            float4 vv = vsrc[r * 16 + c];
            *reinterpret_cast<float4*>(&Ks[r][c * 4]) = kv;
            *reinterpret_cast<float4*>(&Vs[r][c * 4]) = vv;
        }
        __syncthreads();

        // scores for this thread's 16 keys (k = 4i+seg), full d=64 dot
        float s[16];
#pragma unroll
        for (int i = 0; i < 16; ++i) {
            int key = 4 * i + seg;
            const ulonglong2* kp =
                reinterpret_cast<const ulonglong2*>(&Ks[key][0]);
            ulonglong2 t0 = kp[0];
            unsigned long long s2a, s2b;
            MUL2(s2a, q2[0], t0.x);
            MUL2(s2b, q2[1], t0.y);
#pragma unroll
            for (int j2 = 1; j2 < 16; ++j2) {
                ulonglong2 t = kp[j2];
                FMA2(s2a, q2[2 * j2], t.x);
                FMA2(s2b, q2[2 * j2 + 1], t.y);
            }
            ADD2(s2a, s2a, s2b);
            unsigned lo, hi; UNPK2(lo, hi, s2a);
            s[i] = __uint_as_float(lo) + __uint_as_float(hi);
        }
        if (kt == qt) {   // causal mask inside diagonal tile
#pragma unroll
            for (int i = 0; i < 16; ++i)
                if (kt * 64 + 4 * i + seg > row_g) s[i] = -1e30f;
        }

        float cmax = s[0];
#pragma unroll
        for (int i = 1; i < 16; ++i) cmax = fmaxf(cmax, s[i]);
        cmax = fmaxf(cmax, __shfl_xor_sync(0xffffffffu, cmax, 1));
        cmax = fmaxf(cmax, __shfl_xor_sync(0xffffffffu, cmax, 2));
        float mt = fmaxf(m, cmax);
        float corr = __expf(m - mt);
        float pown[16];
        float psum = 0.f;
#pragma unroll
        for (int i = 0; i < 16; ++i) {
            pown[i] = __expf(s[i] - mt);
            psum += pown[i];
        }
        psum += __shfl_xor_sync(0xffffffffu, psum, 1);
        psum += __shfl_xor_sync(0xffffffffu, psum, 2);
        l = l * corr + psum;
        m = mt;

        unsigned long long c2; DUP2(c2, corr);
#pragma unroll
        for (int j = 0; j < 32; ++j) MUL2(o2[j], o2[j], c2);

#pragma unroll
        for (int i = 0; i < 16; ++i) {
            int key = 4 * i + seg;
            unsigned long long p2; DUP2(p2, pown[i]);
            const ulonglong2* vp =
                reinterpret_cast<const ulonglong2*>(&Vs[key][0]);
#pragma unroll
            for (int j2 = 0; j2 < 16; ++j2) {
                ulonglong2 t = vp[j2];
                FMA2(o2[2 * j2], p2, t.x);
                FMA2(o2[2 * j2 + 1], p2, t.y);
            }
        }
        __syncthreads();
    }

    // cross-seg reduction of o (once per block)
#pragma unroll
    for (int j = 0; j < 32; ++j) {
        unsigned long long t = __shfl_xor_sync(0xffffffffu, o2[j], 1);
        ADD2(o2[j], o2[j], t);
        t = __shfl_xor_sync(0xffffffffu, o2[j], 2);
        ADD2(o2[j], o2[j], t);
    }
    unsigned long long inv2; DUP2(inv2, 1.0f / l);
#pragma unroll
    for (int j = 0; j < 32; ++j) MUL2(o2[j], o2[j], inv2);

    ulonglong2* dst = reinterpret_cast<ulonglong2*>(
        g_C + (((size_t)n * BT + (size_t)qt * 64 + row) * BH + h) * DH);
#define STORE_SEG(S) \
    { ulonglong2 v; \
      v.x = o2[S * 8 + 0]; v.y = o2[S * 8 + 1]; dst[S * 4 + 0] = v; \
      v.x = o2[S * 8 + 2]; v.y = o2[S * 8 + 3]; dst[S * 4 + 1] = v; \
      v.x = o2[S * 8 + 4]; v.y = o2[S * 8 + 5]; dst[S * 4 + 2] = v; \
      v.x = o2[S * 8 + 6]; v.y = o2[S * 8 + 7]; dst[S * 4 + 3] = v; }
    switch (seg) {
        case 0: STORE_SEG(0); break;
        case 1: STORE_SEG(1); break;
        case 2: STORE_SEG(2); break;
        default: STORE_SEG(3); break;
    }
#undef STORE_SEG
}

// ---------------------------------------------------------------------------
// Output projection: out[r, e] = sum_k C[r, k] * Wo[e, k] + bo[e]
// 128r x 64c tile, microtile 8r x 4c, f32x2 packed over c-pairs.
// ---------------------------------------------------------------------------
__global__ __launch_bounds__(256) void outproj_kernel(
    const float* __restrict__ Wo, const float* __restrict__ bo,
    float* __restrict__ out)
{
    int r0 = blockIdx.x * 128;
    int c0 = blockIdx.y * 64;

    __shared__ __align__(16) float As[16][132];  // [k][r]
    __shared__ __align__(16) float Bs[16][68];   // [k][c]

    int tid = threadIdx.x;
    int ty = tid >> 4, tx = tid & 15;

    unsigned long long acc2[8][2];
#pragma unroll
    for (int i = 0; i < 8; i++) { acc2[i][0] = 0ULL; acc2[i][1] = 0ULL; }

    for (int k0 = 0; k0 < BE; k0 += 16) {
#pragma unroll
        for (int it = 0; it < 8; ++it) {              // 128x16
            int li = tid + it * 256;
            int c = li & 15, r = li >> 4;
            As[c][r] = g_C[(size_t)(r0 + r) * BE + k0 + c];
        }
#pragma unroll
        for (int it = 0; it < 4; ++it) {              // 16k x 64c
            int li = tid + it * 256;
            int kk = li & 15, c = li >> 4;
            Bs[kk][c] = Wo[(size_t)(c0 + c) * BE + k0 + kk];
        }
        __syncthreads();
#pragma unroll
        for (int kk = 0; kk < 16; ++kk) {
            float4 a0 = *reinterpret_cast<const float4*>(&As[kk][ty * 8]);
            float4 a1 = *reinterpret_cast<const float4*>(&As[kk][ty * 8 + 4]);
            ulonglong2 b = *reinterpret_cast<const ulonglong2*>(&Bs[kk][tx * 4]);
            unsigned long long da;
            DUP2(da, a0.x); FMA2(acc2[0][0], da, b.x); FMA2(acc2[0][1], da, b.y);
            DUP2(da, a0.y); FMA2(acc2[1][0], da, b.x); FMA2(acc2[1][1], da, b.y);
            DUP2(da, a0.z); FMA2(acc2[2][0], da, b.x); FMA2(acc2[2][1], da, b.y);
            DUP2(da, a0.w); FMA2(acc2[3][0], da, b.x); FMA2(acc2[3][1], da, b.y);
            DUP2(da, a1.x); FMA2(acc2[4][0], da, b.x); FMA2(acc2[4][1], da, b.y);
            DUP2(da, a1.y); FMA2(acc2[5][0], da, b.x); FMA2(acc2[5][1], da, b.y);
            DUP2(da, a1.z); FMA2(acc2[6][0], da, b.x); FMA2(acc2[6][1], da, b.y);
            DUP2(da, a1.w); FMA2(acc2[7][0], da, b.x); FMA2(acc2[7][1], da, b.y);
        }
        __syncthreads();
    }
#pragma unroll
    for (int i = 0; i < 8; i++) {
        unsigned p0, p1, p2, p3;
        UNPK2(p0, p1, acc2[i][0]);
        UNPK2(p2, p3, acc2[i][1]);
        int c = c0 + tx * 4;
        float4 v = make_float4(__uint_as_float(p0) + bo[c + 0],
                               __uint_as_float(p1) + bo[c + 1],
                               __uint_as_float(p2) + bo[c + 2],
                               __uint_as_float(p3) + bo[c + 3]);
        *reinterpret_cast<float4*>(&out[(size_t)(r0 + ty * 8 + i) * BE + c]) = v;
    }
}

// ---------------------------------------------------------------------------
extern "C" void kernel_launch(void* const* d_in, const int* in_sizes, int n_in,
                              void* d_out, int out_size)
{
    const float* q  = (const float*)d_in[0];
    const float* k  = (const float*)d_in[1];
    const float* v  = (const float*)d_in[2];
    // d_in[3] = mask (int32 tril) — causality implemented structurally
    const float* Wq = (const float*)d_in[4];
    const float* Wk = (const float*)d_in[5];
    const float* Wv = (const float*)d_in[6];
    const float* Wo = (const float*)d_in[7];
    const float* bo = (const float*)d_in[8];
    float* out = (float*)d_out;

    proj_kernel<<<dim3(BT / 128, BN * BH, 3), 256>>>(q, k, v, Wq, Wk, Wv);
    flash_kernel<<<dim3(BT / 64, BN * BH), 256>>>();
    outproj_kernel<<<dim3(BN * BT / 128, BE / 64), 256>>>(Wo, bo, out);
}